// round 9
// baseline (speedup 1.0000x reference)
#include <cuda_runtime.h>
#include <cstdint>

#define BATCH 4
#define SEQ   4096
#define CH    1024
#define HS    64

__device__ float g_q[BATCH*SEQ*HS];
__device__ float g_k[BATCH*SEQ*HS];
__device__ float g_v[BATCH*SEQ*HS];

// ---------------------------------------------------------------- primitives
__device__ __forceinline__ uint32_t smem_u32(const void* p){
    uint32_t a;
    asm("{ .reg .u64 t; cvta.to.shared.u64 t, %1; cvt.u32.u64 %0, t; }":"=r"(a):"l"(p));
    return a;
}
__device__ __forceinline__ uint32_t f2tf(float f){
    uint32_t u; asm("cvt.rna.tf32.f32 %0, %1;" : "=r"(u) : "f"(f)); return u;
}
__device__ __forceinline__ float ex2f(float x){
    float y; asm("ex2.approx.ftz.f32 %0, %1;" : "=f"(y) : "f"(x)); return y;
}
__device__ __forceinline__ void mma8(float* d, const uint32_t* a, const uint32_t* b){
    asm volatile("mma.sync.aligned.m16n8k8.row.col.f32.tf32.tf32.f32 "
        "{%0,%1,%2,%3}, {%4,%5,%6,%7}, {%8,%9}, {%0,%1,%2,%3};"
        : "+f"(d[0]), "+f"(d[1]), "+f"(d[2]), "+f"(d[3])
        : "r"(a[0]), "r"(a[1]), "r"(a[2]), "r"(a[3]), "r"(b[0]), "r"(b[1]));
}
#define LDSM4(r0,r1,r2,r3,addr)                                              \
    asm volatile("ldmatrix.sync.aligned.m8n8.x4.shared.b16 {%0,%1,%2,%3}, [%4];" \
        : "=r"(r0), "=r"(r1), "=r"(r2), "=r"(r3) : "r"(addr))

#define BARG(id) asm volatile("bar.sync %0, 256;" :: "r"(id) : "memory")
#define C_EXP 0.18033688011112042f   // (1/8) * log2(e)

// ---------------------------------------------------------------- QKV kernel
// grid 128, block 512 (16 warps). 128 rows/CTA, warps split N=192 two ways.
// Natural layout + ldmatrix fragment loads.  (unchanged from round 6)
#define QKV_SMEM ((128*68 + 192*68) * 4)
__global__ __launch_bounds__(512, 1) void qkv_tc(
    const float* __restrict__ x,  const float* __restrict__ Wq,
    const float* __restrict__ Wk, const float* __restrict__ Wv)
{
    extern __shared__ __align__(16) uint32_t sm[];
    uint32_t* xs = sm;             // [128 rows][68] natural (row stride 272B)
    uint32_t* wt = sm + 128*68;    // [192 n  ][68] natural
    const int tid = threadIdx.x, w = tid >> 5, ln = tid & 31;
    const int m = ln & 3, qr = ln >> 2;
    const int wh = w >> 3;          // n-half (0..1)
    const int wrow = (w & 7) * 16;  // warp's row base
    const int row0 = blockIdx.x * 128;
    const float* Ws[3] = {Wq, Wk, Wv};

    const int l7 = ln & 7, l3 = (ln >> 3) & 1, l4 = (ln >> 4) & 1;
    const uint32_t offA  = (uint32_t)((l7 + l3*8)*272 + l4*16);   // A frag x4
    const uint32_t offWB = (uint32_t)((l7 + l4*8)*272 + l3*16);   // B pair x4
    const uint32_t XB = smem_u32(xs), WB = smem_u32(wt);

    float o[12][4];
    #pragma unroll
    for (int i = 0; i < 12; i++) { o[i][0]=o[i][1]=o[i][2]=o[i][3]=0.f; }

    const int wr = tid & 63;        // W fill: k-row
    const int wg = tid >> 6;        // hs octant (0..7)

    #pragma unroll 1
    for (int c = 0; c < 16; c++) {
        const int k0 = c * 64;
        #pragma unroll
        for (int i = 0; i < 4; i++) {
            int idx = tid + i*512, r = idx >> 4, c4 = idx & 15;
            float4 v = *(const float4*)(x + (size_t)(row0+r)*CH + k0 + c4*4);
            uint4 u = make_uint4(f2tf(v.x), f2tf(v.y), f2tf(v.z), f2tf(v.w));
            *(uint4*)((char*)xs + r*272 + c4*16) = u;
        }
        #pragma unroll
        for (int ww = 0; ww < 3; ww++) {
            #pragma unroll
            for (int j = 0; j < 2; j++) {
                int hs0 = wg*8 + j*4;
                float4 v = *(const float4*)(Ws[ww] + (size_t)(k0+wr)*HS + hs0);
                wt[(ww*64 + hs0+0)*68 + wr] = f2tf(v.x);
                wt[(ww*64 + hs0+1)*68 + wr] = f2tf(v.y);
                wt[(ww*64 + hs0+2)*68 + wr] = f2tf(v.z);
                wt[(ww*64 + hs0+3)*68 + wr] = f2tf(v.w);
            }
        }
        __syncthreads();

        #pragma unroll 1
        for (int ks = 0; ks < 8; ks++) {
            uint32_t a[4];
            LDSM4(a[0], a[1], a[2], a[3], XB + (uint32_t)(wrow*272 + ks*32) + offA);
            #pragma unroll
            for (int np = 0; np < 6; np++) {
                uint32_t bf[4];
                LDSM4(bf[0], bf[1], bf[2], bf[3],
                      WB + (uint32_t)(((wh*12 + 2*np)*8)*272 + ks*32) + offWB);
                mma8(o[2*np],   a, bf);
                mma8(o[2*np+1], a, bf+2);
            }
        }
        __syncthreads();
    }
    float* dsts[3] = {g_q, g_k, g_v};
    const int rg = row0 + wrow + qr;
    #pragma unroll
    for (int nt = 0; nt < 12; nt++) {
        int ntg = wh*12 + nt;
        float* d = dsts[ntg >> 3];
        int col = (ntg & 7)*8 + 2*m;
        *(float2*)(d + (size_t)rg*HS + col)     = make_float2(o[nt][0], o[nt][1]);
        *(float2*)(d + (size_t)(rg+8)*HS + col) = make_float2(o[nt][2], o[nt][3]);
    }
}

// ----------------------------------------------------------- attention kernel
// grid 128 (4b x 32 qtiles of 128), block 512 = 2 groups x 256.
// Group g: key tiles jt = g, g+2, ... (split-K; no max subtraction => O,l
// purely additive). Q frags register-resident via ldmatrix.
// S->P conversion via warp-private smem round-trip (STS.64 + ldmatrix).
// P buffer row stride = 36 words (144B = odd multiple of 16B): ldmatrix
// row addresses stay 16B-aligned (34-word stride trapped: misaligned address).
#define GRP_WORDS (128*68 + 64*132)
#define PS_WORDS  (16*36)                       // per-warp P chunk buffer
#define ATT_SMEM ((2*GRP_WORDS + 16*PS_WORDS) * 4)
__global__ __launch_bounds__(512, 1) void attn_tc(float* __restrict__ out)
{
    extern __shared__ __align__(16) uint32_t sm[];
    const int tid = threadIdx.x, w = tid >> 5, ln = tid & 31;
    const int m = ln & 3, qr = ln >> 2;
    const int g = w >> 3;              // key-parity group
    const int gtid = tid & 255;
    const int wrow = (w & 7) * 16;     // warp's 16 query rows
    uint32_t* Kg  = sm + g*GRP_WORDS;  // [128 key][68] natural (272B rows)
    uint32_t* VTg = Kg + 128*68;       // [64 hs ][132] natural (528B rows)
    uint32_t* Psw = sm + 2*GRP_WORDS + w*PS_WORDS;  // [16 q][36] P chunk
    const int b = blockIdx.x >> 5, qt = blockIdx.x & 31;
    const float* qg = g_q + ((size_t)b*SEQ + qt*128) * HS;
    const float* kg = g_k + (size_t)b*SEQ*HS;
    const float* vg = g_v + (size_t)b*SEQ*HS;

    const int l7 = ln & 7, l3 = (ln >> 3) & 1, l4 = (ln >> 4) & 1;
    const uint32_t offKB = (uint32_t)(l7*272 + (ln >> 3)*16);       // B pairs (ks,ks+1)
    const uint32_t offA  = (uint32_t)((l7 + l3*8)*272 + l4*16);     // A frag (272B rows)
    const uint32_t offVT = (uint32_t)((l7 + l4*8)*528 + l3*16);     // VT B pairs (n,n+1)
    const uint32_t offPA = (uint32_t)((l7 + l3*8)*144 + l4*16);     // P A frag (144B rows)
    const uint32_t KB = smem_u32(Kg), VB = smem_u32(VTg);
    const uint32_t SB = smem_u32(sm), PB = smem_u32(Psw);

    // stage Q natural into group-0 area (all 512 threads), pull frags, release
    #pragma unroll
    for (int i = 0; i < 4; i++) {
        int idx = tid + i*512, r = idx >> 4, c4 = idx & 15;
        float4 v = *(const float4*)(qg + (size_t)r*HS + c4*4);
        uint4 u = make_uint4(f2tf(v.x), f2tf(v.y), f2tf(v.z), f2tf(v.w));
        *(uint4*)((char*)sm + r*272 + c4*16) = u;
    }
    __syncthreads();
    uint32_t q[8][4];
    {
        uint32_t qb = SB + (uint32_t)(wrow*272) + offA;
        #pragma unroll
        for (int ks = 0; ks < 8; ks++)
            LDSM4(q[ks][0], q[ks][1], q[ks][2], q[ks][3], qb + ks*32);
    }
    __syncthreads();

    float o[8][4];
    #pragma unroll
    for (int nt = 0; nt < 8; nt++) { o[nt][0]=o[nt][1]=o[nt][2]=o[nt][3]=0.f; }
    float l0 = 0.f, l1 = 0.f;

    #pragma unroll 1
    for (int jt = g; jt <= qt; jt += 2) {
        const float* kt = kg + (size_t)jt*128*HS;
        const float* vt = vg + (size_t)jt*128*HS;
        // K fill: natural, STS.128
        #pragma unroll
        for (int i = 0; i < 8; i++) {
            int idx = gtid + i*256, r = idx >> 4, c4 = idx & 15;
            float4 v = *(const float4*)(kt + (size_t)r*HS + c4*4);
            uint4 u = make_uint4(f2tf(v.x), f2tf(v.y), f2tf(v.z), f2tf(v.w));
            *(uint4*)((char*)Kg + r*272 + c4*16) = u;
        }
        // VT fill transposed: VT[hs][key] natural
        {
            int kr = gtid & 127, half = gtid >> 7;
            #pragma unroll
            for (int j = 0; j < 8; j++) {
                int hs0 = half*32 + j*4;
                float4 v = *(const float4*)(vt + (size_t)kr*HS + hs0);
                VTg[(hs0+0)*132 + kr] = f2tf(v.x);
                VTg[(hs0+1)*132 + kr] = f2tf(v.y);
                VTg[(hs0+2)*132 + kr] = f2tf(v.z);
                VTg[(hs0+3)*132 + kr] = f2tf(v.w);
            }
        }
        BARG(g+1);

        const bool diag = (jt == qt);
        const int rg0 = qt*128 + wrow + qr;
        const int rg1 = rg0 + 8;
        #pragma unroll 1
        for (int ch = 0; ch < 4; ch++) {
            float s[4][4];
            #pragma unroll
            for (int nt = 0; nt < 4; nt++)
                { s[nt][0]=s[nt][1]=s[nt][2]=s[nt][3]=0.f; }
            // S = Q K^T, ks processed in pairs via LDSM.x4
            #pragma unroll
            for (int ksp = 0; ksp < 4; ksp++) {
                #pragma unroll
                for (int nt = 0; nt < 4; nt++) {
                    uint32_t bf[4];
                    LDSM4(bf[0], bf[1], bf[2], bf[3],
                          KB + (uint32_t)((ch*32 + nt*8)*272 + ksp*64) + offKB);
                    mma8(s[nt], q[2*ksp],   bf);
                    mma8(s[nt], q[2*ksp+1], bf+2);
                }
            }
            // softmax; P chunk -> warp-private smem (STS.64 pairs)
            #pragma unroll
            for (int nt = 0; nt < 4; nt++) {
                const int kb = ch*32 + nt*8;
                const int kg0 = jt*128 + kb + 2*m;
                float p0 = ex2f(s[nt][0] * C_EXP);
                float p1 = ex2f(s[nt][1] * C_EXP);
                float p2 = ex2f(s[nt][2] * C_EXP);
                float p3 = ex2f(s[nt][3] * C_EXP);
                if (diag) {
                    if (kg0     > rg0) p0 = 0.f;
                    if (kg0 + 1 > rg0) p1 = 0.f;
                    if (kg0     > rg1) p2 = 0.f;
                    if (kg0 + 1 > rg1) p3 = 0.f;
                }
                uint32_t u0 = f2tf(p0), u1 = f2tf(p1), u2 = f2tf(p2), u3 = f2tf(p3);
                l0 += __uint_as_float(u0) + __uint_as_float(u1);
                l1 += __uint_as_float(u2) + __uint_as_float(u3);
                *(uint2*)&Psw[qr*36     + nt*8 + 2*m] = make_uint2(u0, u1);
                *(uint2*)&Psw[(qr+8)*36 + nt*8 + 2*m] = make_uint2(u2, u3);
            }
            __syncwarp();
            // O += P_chunk @ V_chunk : A frags from Psw via ldmatrix
            #pragma unroll
            for (int kb = 0; kb < 4; kb++) {
                uint32_t a[4];
                LDSM4(a[0], a[1], a[2], a[3], PB + (uint32_t)(kb*32) + offPA);
                #pragma unroll
                for (int np = 0; np < 4; np++) {
                    uint32_t vb[4];
                    LDSM4(vb[0], vb[1], vb[2], vb[3],
                          VB + (uint32_t)((2*np*8)*528 + (ch*32 + kb*8)*4) + offVT);
                    mma8(o[2*np],   a, vb);
                    mma8(o[2*np+1], a, vb+2);
                }
            }
            __syncwarp();   // protect Psw before next chunk's stores
        }
        BARG(g+1);   // group done reading Kg/VTg before next fill
    }

    // ---- combine the two split-K partials ----
    __syncthreads();
    l0 += __shfl_xor_sync(0xffffffffu, l0, 1);
    l0 += __shfl_xor_sync(0xffffffffu, l0, 2);
    l1 += __shfl_xor_sync(0xffffffffu, l1, 1);
    l1 += __shfl_xor_sync(0xffffffffu, l1, 2);

    float* Obuf = (float*)sm;            // [128][66]
    float* lbuf = (float*)sm + 128*66;   // [128]
    if (g == 0) {
        #pragma unroll
        for (int nt = 0; nt < 8; nt++) {
            *(float2*)&Obuf[(wrow+qr)*66 + nt*8 + 2*m]   = make_float2(o[nt][0], o[nt][1]);
            *(float2*)&Obuf[(wrow+qr+8)*66 + nt*8 + 2*m] = make_float2(o[nt][2], o[nt][3]);
        }
        if (m == 0) { lbuf[wrow+qr] = l0; lbuf[wrow+qr+8] = l1; }
    }
    __syncthreads();
    if (g == 1) {
        float inv0 = 1.f / (l0 + lbuf[wrow+qr]);
        float inv1 = 1.f / (l1 + lbuf[wrow+qr+8]);
        float* d = out + ((size_t)b*SEQ + qt*128 + wrow + qr) * HS;
        #pragma unroll
        for (int nt = 0; nt < 8; nt++) {
            float2 b0 = *(float2*)&Obuf[(wrow+qr)*66 + nt*8 + 2*m];
            float2 b1 = *(float2*)&Obuf[(wrow+qr+8)*66 + nt*8 + 2*m];
            *(float2*)(d + nt*8 + 2*m) =
                make_float2((o[nt][0]+b0.x)*inv0, (o[nt][1]+b0.y)*inv0);
            *(float2*)(d + (size_t)8*HS + nt*8 + 2*m) =
                make_float2((o[nt][2]+b1.x)*inv1, (o[nt][3]+b1.y)*inv1);
        }
    }
}

// ---------------------------------------------------------------------------
extern "C" void kernel_launch(void* const* d_in, const int* in_sizes, int n_in,
                              void* d_out, int out_size)
{
    const float* x  = (const float*)d_in[0];
    const float* Wq = (const float*)d_in[1];
    const float* Wk = (const float*)d_in[2];
    const float* Wv = (const float*)d_in[3];
    float* out = (float*)d_out;

    cudaFuncSetAttribute(qkv_tc,  cudaFuncAttributeMaxDynamicSharedMemorySize, QKV_SMEM);
    cudaFuncSetAttribute(attn_tc, cudaFuncAttributeMaxDynamicSharedMemorySize, ATT_SMEM);

    qkv_tc<<<128, 512, QKV_SMEM>>>(x, Wq, Wk, Wv);
    attn_tc<<<128, 512, ATT_SMEM>>>(out);
}

// round 11
// speedup vs baseline: 1.8330x; 1.8330x over previous
#include <cuda_runtime.h>
#include <cuda_fp16.h>
#include <cstdint>

#define BATCH 4
#define SEQ   4096
#define CH    1024
#define HS    64

__device__ __half g_q[BATCH*SEQ*HS];
__device__ __half g_k[BATCH*SEQ*HS];
__device__ __half g_v[BATCH*SEQ*HS];

// ---------------------------------------------------------------- primitives
__device__ __forceinline__ uint32_t smem_u32(const void* p){
    uint32_t a;
    asm("{ .reg .u64 t; cvta.to.shared.u64 t, %1; cvt.u32.u64 %0, t; }":"=r"(a):"l"(p));
    return a;
}
__device__ __forceinline__ float ex2f(float x){
    float y; asm("ex2.approx.ftz.f32 %0, %1;" : "=f"(y) : "f"(x)); return y;
}
__device__ __forceinline__ uint32_t packh2(float lo, float hi){
    uint32_t u;
    asm("cvt.rn.f16x2.f32 %0, %2, %1;" : "=r"(u) : "f"(lo), "f"(hi));
    return u;
}
// D(16x8,f32) += A(16x16,f16) * B(16x8,f16)
__device__ __forceinline__ void mma16(float* d, const uint32_t* a, const uint32_t* b){
    asm volatile("mma.sync.aligned.m16n8k16.row.col.f32.f16.f16.f32 "
        "{%0,%1,%2,%3}, {%4,%5,%6,%7}, {%8,%9}, {%0,%1,%2,%3};"
        : "+f"(d[0]), "+f"(d[1]), "+f"(d[2]), "+f"(d[3])
        : "r"(a[0]), "r"(a[1]), "r"(a[2]), "r"(a[3]), "r"(b[0]), "r"(b[1]));
}
#define LDSM4(r0,r1,r2,r3,addr)                                              \
    asm volatile("ldmatrix.sync.aligned.m8n8.x4.shared.b16 {%0,%1,%2,%3}, [%4];" \
        : "=r"(r0), "=r"(r1), "=r"(r2), "=r"(r3) : "r"(addr))
#define LDSM4T(r0,r1,r2,r3,addr)                                             \
    asm volatile("ldmatrix.sync.aligned.m8n8.x4.trans.shared.b16 {%0,%1,%2,%3}, [%4];" \
        : "=r"(r0), "=r"(r1), "=r"(r2), "=r"(r3) : "r"(addr))

#define BARG(id) asm volatile("bar.sync %0, 256;" :: "r"(id) : "memory")
#define C_EXP 0.18033688011112042f   // (1/8) * log2(e)

#define KSTR 144    // Q/K/V/x/W smem row stride (bytes) = 9*16, odd multiple
#define PSTR 80     // P buffer row stride = 5*16, odd multiple

// ---------------------------------------------------------------- QKV kernel
// grid 128, block 512 (16 warps). 128 rows/CTA; warps: 8 row-tiles x 2 n-halves
// of the fused N=192 (q|k|v). fp16 operands, fp32 accum; outputs fp16.
#define QKV_SMEM (128*KSTR + 192*KSTR)
__global__ __launch_bounds__(512, 1) void qkv_tc(
    const float* __restrict__ x,  const float* __restrict__ Wq,
    const float* __restrict__ Wk, const float* __restrict__ Wv)
{
    extern __shared__ __align__(16) char sm[];
    char* xs = sm;                 // [128 rows][64 k] fp16, 144B rows
    __half* wt = (__half*)(sm + 128*KSTR);   // [192 n][72] fp16 (144B rows)
    const int tid = threadIdx.x, w = tid >> 5, ln = tid & 31;
    const int m = ln & 3, qr = ln >> 2;
    const int wh = w >> 3;          // n-half (0..1)
    const int wrow = (w & 7) * 16;  // warp's row base
    const int row0 = blockIdx.x * 128;
    const float* Ws[3] = {Wq, Wk, Wv};

    const int l7 = ln & 7, l3 = (ln >> 3) & 1, l4 = (ln >> 4) & 1;
    const uint32_t offA  = (uint32_t)((l7 + l3*8)*KSTR + l4*16);  // A frag x4
    const uint32_t offB  = (uint32_t)(l7*KSTR + (ln >> 3)*16);    // B 2-kstep x4
    const uint32_t XB = smem_u32(xs), WB = smem_u32(wt);

    float o[12][4];
    #pragma unroll
    for (int i = 0; i < 12; i++) { o[i][0]=o[i][1]=o[i][2]=o[i][3]=0.f; }

    const int wr = tid & 63;        // W fill: k-row
    const int wg = tid >> 6;        // hs octant (0..7)

    #pragma unroll 1
    for (int c = 0; c < 16; c++) {
        const int k0 = c * 64;
        // x tile fill: [128][64] fp16
        #pragma unroll
        for (int i = 0; i < 4; i++) {
            int idx = tid + i*512, r = idx >> 4, c4 = idx & 15;
            float4 v = *(const float4*)(x + (size_t)(row0+r)*CH + k0 + c4*4);
            uint2 u = make_uint2(packh2(v.x, v.y), packh2(v.z, v.w));
            *(uint2*)(xs + r*KSTR + c4*8) = u;
        }
        // W fill transposed: wt[n][k] fp16
        #pragma unroll
        for (int ww = 0; ww < 3; ww++) {
            #pragma unroll
            for (int j = 0; j < 2; j++) {
                int hs0 = wg*8 + j*4;
                float4 v = *(const float4*)(Ws[ww] + (size_t)(k0+wr)*HS + hs0);
                wt[(ww*64 + hs0+0)*72 + wr] = __float2half(v.x);
                wt[(ww*64 + hs0+1)*72 + wr] = __float2half(v.y);
                wt[(ww*64 + hs0+2)*72 + wr] = __float2half(v.z);
                wt[(ww*64 + hs0+3)*72 + wr] = __float2half(v.w);
            }
        }
        __syncthreads();

        #pragma unroll
        for (int ksh = 0; ksh < 2; ksh++) {     // k-halves of 32
            uint32_t a[2][4];
            LDSM4(a[0][0], a[0][1], a[0][2], a[0][3],
                  XB + (uint32_t)(wrow*KSTR + ksh*64) + offA);
            LDSM4(a[1][0], a[1][1], a[1][2], a[1][3],
                  XB + (uint32_t)(wrow*KSTR + ksh*64 + 32) + offA);
            #pragma unroll
            for (int nt = 0; nt < 12; nt++) {
                uint32_t bf[4];
                LDSM4(bf[0], bf[1], bf[2], bf[3],
                      WB + (uint32_t)((wh*96 + nt*8)*KSTR + ksh*64) + offB);
                mma16(o[nt], a[0], bf);
                mma16(o[nt], a[1], bf+2);
            }
        }
        __syncthreads();
    }
    __half* dsts[3] = {g_q, g_k, g_v};
    const int rg = row0 + wrow + qr;
    #pragma unroll
    for (int nt = 0; nt < 12; nt++) {
        int ntg = wh*96 + nt*8;
        __half* d = dsts[ntg >> 6];
        int col = (ntg & 63) + 2*m;
        *(__half2*)(d + (size_t)rg*HS + col) =
            __floats2half2_rn(o[nt][0], o[nt][1]);
        *(__half2*)(d + (size_t)(rg+8)*HS + col) =
            __floats2half2_rn(o[nt][2], o[nt][3]);
    }
}

// ----------------------------------------------------------- attention kernel
// grid 128 (4b x 32 qtiles of 128), block 512 = 2 groups x 256.
// Group g: key tiles jt = g, g+2, ... (split-K; no max subtraction => O,l
// purely additive). fp16 operands (same 10-bit mantissa as tf32), fp32 accum.
// Q frags register-resident; V B-frags via ldmatrix.trans on natural layout.
#define GRP_BYTES (2*128*KSTR)                  // K + V tiles
#define PS_BYTES  (16*PSTR)                     // per-warp P chunk buffer
#define ATT_SMEM (2*GRP_BYTES + 16*PS_BYTES)
__global__ __launch_bounds__(512, 1) void attn_tc(float* __restrict__ out)
{
    extern __shared__ __align__(16) char sm[];
    const int tid = threadIdx.x, w = tid >> 5, ln = tid & 31;
    const int m = ln & 3, qr = ln >> 2;
    const int g = w >> 3;              // key-parity group
    const int gtid = tid & 255;
    const int wrow = (w & 7) * 16;     // warp's 16 query rows
    char* Kg  = sm + g*GRP_BYTES;      // [128 key][64 hs] fp16, 144B rows
    char* Vg  = Kg + 128*KSTR;         // [128 key][64 hs] fp16, natural
    char* Psw = sm + 2*GRP_BYTES + w*PS_BYTES;   // [16 q][32 key] fp16, 80B rows
    const int b = blockIdx.x >> 5, qt = blockIdx.x & 31;
    const __half* qg = g_q + ((size_t)b*SEQ + qt*128) * HS;
    const __half* kg = g_k + (size_t)b*SEQ*HS;
    const __half* vg = g_v + (size_t)b*SEQ*HS;

    const int l7 = ln & 7, l3 = (ln >> 3) & 1, l4 = (ln >> 4) & 1;
    const uint32_t offA  = (uint32_t)((l7 + l3*8)*KSTR + l4*16);   // Q/A frag
    const uint32_t offKB = (uint32_t)(l7*KSTR + (ln >> 3)*16);     // K B 2-kstep
    const uint32_t offVB = (uint32_t)((l7 + l3*8)*KSTR + l4*16);   // V trans B
    const uint32_t offPA = (uint32_t)((l7 + l3*8)*PSTR + l4*16);   // P A frag
    const uint32_t KB = smem_u32(Kg), VB = smem_u32(Vg);
    const uint32_t SB = smem_u32(sm), PB = smem_u32(Psw);

    // stage Q (fp16) into group-0 K area, pull frags, release
    #pragma unroll
    for (int i = 0; i < 2; i++) {
        int idx = tid + i*512, r = idx >> 3, c8 = idx & 7;
        *(uint4*)(sm + r*KSTR + c8*16) = *(const uint4*)(qg + (size_t)r*HS + c8*8);
    }
    __syncthreads();
    uint32_t q[4][4];
    {
        uint32_t qb = SB + (uint32_t)(wrow*KSTR) + offA;
        #pragma unroll
        for (int ks = 0; ks < 4; ks++)
            LDSM4(q[ks][0], q[ks][1], q[ks][2], q[ks][3], qb + ks*32);
    }
    __syncthreads();

    float o[8][4];
    #pragma unroll
    for (int nt = 0; nt < 8; nt++) { o[nt][0]=o[nt][1]=o[nt][2]=o[nt][3]=0.f; }
    float l0 = 0.f, l1 = 0.f;

    #pragma unroll 1
    for (int jt = g; jt <= qt; jt += 2) {
        const __half* kt = kg + (size_t)jt*128*HS;
        const __half* vt = vg + (size_t)jt*128*HS;
        // K and V fills: straight fp16 copies, STS.128
        #pragma unroll
        for (int i = 0; i < 4; i++) {
            int idx = gtid + i*256, r = idx >> 3, c8 = idx & 7;
            *(uint4*)(Kg + r*KSTR + c8*16) = *(const uint4*)(kt + (size_t)r*HS + c8*8);
            *(uint4*)(Vg + r*KSTR + c8*16) = *(const uint4*)(vt + (size_t)r*HS + c8*8);
        }
        BARG(g+1);

        const bool diag = (jt == qt);
        const int rg0 = qt*128 + wrow + qr;
        const int rg1 = rg0 + 8;
        #pragma unroll 1
        for (int ch = 0; ch < 4; ch++) {
            float s[4][4];
            #pragma unroll
            for (int nt = 0; nt < 4; nt++)
                { s[nt][0]=s[nt][1]=s[nt][2]=s[nt][3]=0.f; }
            // S = Q K^T : per n-block, two x4 loads cover all 4 k-steps
            #pragma unroll
            for (int nt = 0; nt < 4; nt++) {
                const uint32_t krow = (uint32_t)((ch*32 + nt*8)*KSTR);
                uint32_t bf[4];
                LDSM4(bf[0], bf[1], bf[2], bf[3], KB + krow + offKB);
                mma16(s[nt], q[0], bf);
                mma16(s[nt], q[1], bf+2);
                LDSM4(bf[0], bf[1], bf[2], bf[3], KB + krow + 64 + offKB);
                mma16(s[nt], q[2], bf);
                mma16(s[nt], q[3], bf+2);
            }
            // softmax; P chunk -> warp-private smem as fp16 pairs
            #pragma unroll
            for (int nt = 0; nt < 4; nt++) {
                const int kb = ch*32 + nt*8;
                const int kg0 = jt*128 + kb + 2*m;
                float p0 = ex2f(s[nt][0] * C_EXP);
                float p1 = ex2f(s[nt][1] * C_EXP);
                float p2 = ex2f(s[nt][2] * C_EXP);
                float p3 = ex2f(s[nt][3] * C_EXP);
                if (diag) {
                    if (kg0     > rg0) p0 = 0.f;
                    if (kg0 + 1 > rg0) p1 = 0.f;
                    if (kg0     > rg1) p2 = 0.f;
                    if (kg0 + 1 > rg1) p3 = 0.f;
                }
                l0 += p0 + p1;
                l1 += p2 + p3;
                *(uint32_t*)(Psw + qr*PSTR     + nt*16 + m*4) = packh2(p0, p1);
                *(uint32_t*)(Psw + (qr+8)*PSTR + nt*16 + m*4) = packh2(p2, p3);
            }
            __syncwarp();
            // O += P_chunk @ V_chunk : A from P buffer, B via ldmatrix.trans
            #pragma unroll
            for (int kst = 0; kst < 2; kst++) {       // 16 keys each
                uint32_t a[4];
                LDSM4(a[0], a[1], a[2], a[3], PB + (uint32_t)(kst*32) + offPA);
                const uint32_t vrow = (uint32_t)((ch*32 + kst*16)*KSTR);
                #pragma unroll
                for (int np = 0; np < 4; np++) {      // 2 hs n-blocks each
                    uint32_t vb[4];
                    LDSM4T(vb[0], vb[1], vb[2], vb[3],
                           VB + vrow + (uint32_t)(np*32) + offVB);
                    mma16(o[2*np],   a, vb);
                    mma16(o[2*np+1], a, vb+2);
                }
            }
            __syncwarp();   // protect Psw before next chunk's stores
        }
        BARG(g+1);   // group done reading Kg/Vg before next fill
    }

    // ---- combine the two split-K partials ----
    __syncthreads();
    l0 += __shfl_xor_sync(0xffffffffu, l0, 1);
    l0 += __shfl_xor_sync(0xffffffffu, l0, 2);
    l1 += __shfl_xor_sync(0xffffffffu, l1, 1);
    l1 += __shfl_xor_sync(0xffffffffu, l1, 2);

    float* Obuf = (float*)sm;            // [128][66]
    float* lbuf = (float*)sm + 128*66;   // [128]
    if (g == 0) {
        #pragma unroll
        for (int nt = 0; nt < 8; nt++) {
            *(float2*)&Obuf[(wrow+qr)*66 + nt*8 + 2*m]   = make_float2(o[nt][0], o[nt][1]);
            *(float2*)&Obuf[(wrow+qr+8)*66 + nt*8 + 2*m] = make_float2(o[nt][2], o[nt][3]);
        }
        if (m == 0) { lbuf[wrow+qr] = l0; lbuf[wrow+qr+8] = l1; }
    }
    __syncthreads();
    if (g == 1) {
        float inv0 = 1.f / (l0 + lbuf[wrow+qr]);
        float inv1 = 1.f / (l1 + lbuf[wrow+qr+8]);
        float* d = out + ((size_t)b*SEQ + qt*128 + wrow + qr) * HS;
        #pragma unroll
        for (int nt = 0; nt < 8; nt++) {
            float2 b0 = *(float2*)&Obuf[(wrow+qr)*66 + nt*8 + 2*m];
            float2 b1 = *(float2*)&Obuf[(wrow+qr+8)*66 + nt*8 + 2*m];
            *(float2*)(d + nt*8 + 2*m) =
                make_float2((o[nt][0]+b0.x)*inv0, (o[nt][1]+b0.y)*inv0);
            *(float2*)(d + (size_t)8*HS + nt*8 + 2*m) =
                make_float2((o[nt][2]+b1.x)*inv1, (o[nt][3]+b1.y)*inv1);
        }
    }
}

// ---------------------------------------------------------------------------
extern "C" void kernel_launch(void* const* d_in, const int* in_sizes, int n_in,
                              void* d_out, int out_size)
{
    const float* x  = (const float*)d_in[0];
    const float* Wq = (const float*)d_in[1];
    const float* Wk = (const float*)d_in[2];
    const float* Wv = (const float*)d_in[3];
    float* out = (float*)d_out;

    cudaFuncSetAttribute(qkv_tc,  cudaFuncAttributeMaxDynamicSharedMemorySize, QKV_SMEM);
    cudaFuncSetAttribute(attn_tc, cudaFuncAttributeMaxDynamicSharedMemorySize, ATT_SMEM);

    qkv_tc<<<128, 512, QKV_SMEM>>>(x, Wq, Wk, Wv);
    attn_tc<<<128, 512, ATT_SMEM>>>(out);
}

// round 12
// speedup vs baseline: 2.1833x; 1.1911x over previous
#include <cuda_runtime.h>
#include <cuda_fp16.h>
#include <cstdint>

#define BATCH 4
#define SEQ   4096
#define CH    1024
#define HS    64

__device__ __half g_q[BATCH*SEQ*HS];
__device__ __half g_k[BATCH*SEQ*HS];
__device__ __half g_v[BATCH*SEQ*HS];
__device__ __half g_xh[BATCH*SEQ*CH];        // x pre-converted to fp16
__device__ __half g_wt[3*HS*CH];             // W transposed: [n=192][k=1024] fp16

// ---------------------------------------------------------------- primitives
__device__ __forceinline__ uint32_t smem_u32(const void* p){
    uint32_t a;
    asm("{ .reg .u64 t; cvta.to.shared.u64 t, %1; cvt.u32.u64 %0, t; }":"=r"(a):"l"(p));
    return a;
}
__device__ __forceinline__ float ex2f(float x){
    float y; asm("ex2.approx.ftz.f32 %0, %1;" : "=f"(y) : "f"(x)); return y;
}
__device__ __forceinline__ uint32_t packh2(float lo, float hi){
    uint32_t u;
    asm("cvt.rn.f16x2.f32 %0, %2, %1;" : "=r"(u) : "f"(lo), "f"(hi));
    return u;
}
__device__ __forceinline__ void mma16(float* d, const uint32_t* a, const uint32_t* b){
    asm volatile("mma.sync.aligned.m16n8k16.row.col.f32.f16.f16.f32 "
        "{%0,%1,%2,%3}, {%4,%5,%6,%7}, {%8,%9}, {%0,%1,%2,%3};"
        : "+f"(d[0]), "+f"(d[1]), "+f"(d[2]), "+f"(d[3])
        : "r"(a[0]), "r"(a[1]), "r"(a[2]), "r"(a[3]), "r"(b[0]), "r"(b[1]));
}
#define LDSM4(r0,r1,r2,r3,addr)                                              \
    asm volatile("ldmatrix.sync.aligned.m8n8.x4.shared.b16 {%0,%1,%2,%3}, [%4];" \
        : "=r"(r0), "=r"(r1), "=r"(r2), "=r"(r3) : "r"(addr))
#define LDSM4T(r0,r1,r2,r3,addr)                                             \
    asm volatile("ldmatrix.sync.aligned.m8n8.x4.trans.shared.b16 {%0,%1,%2,%3}, [%4];" \
        : "=r"(r0), "=r"(r1), "=r"(r2), "=r"(r3) : "r"(addr))
#define CPA(dst, src) asm volatile("cp.async.cg.shared.global [%0], [%1], 16;" \
        :: "r"(dst), "l"(src) : "memory")
#define CPA_COMMIT() asm volatile("cp.async.commit_group;" ::: "memory")
#define CPA_WAIT0()  asm volatile("cp.async.wait_group 0;" ::: "memory")

#define BARG(id) asm volatile("bar.sync %0, 256;" :: "r"(id) : "memory")
#define C_EXP 0.18033688011112042f   // (1/8) * log2(e)

#define KSTR 144    // fp16 tile row stride (bytes) = 9*16 (ldmatrix-aligned, bank-clean)
#define PSTR 80     // P buffer row stride = 5*16

// ------------------------------------------------------------ convert passes
__global__ __launch_bounds__(512) void cvt_x(const float* __restrict__ x){
    size_t i = ((size_t)blockIdx.x * 512 + threadIdx.x) * 8;
    float4 a = *(const float4*)(x + i);
    float4 b = *(const float4*)(x + i + 4);
    uint4 u = make_uint4(packh2(a.x, a.y), packh2(a.z, a.w),
                         packh2(b.x, b.y), packh2(b.z, b.w));
    *(uint4*)(g_xh + i) = u;
}
__global__ __launch_bounds__(512) void cvt_w(const float* __restrict__ Wq,
                                             const float* __restrict__ Wk,
                                             const float* __restrict__ Wv){
    int idx = blockIdx.x * 512 + threadIdx.x;       // 3*65536 total
    int w = idx >> 16, rem = idx & 65535;
    int k = rem >> 6, n = rem & 63;
    const float* W = (w == 0) ? Wq : (w == 1) ? Wk : Wv;
    g_wt[(size_t)(w*64 + n)*CH + k] = __float2half(W[rem]);
}

// ---------------------------------------------------------------- QKV kernel
// grid 128, block 512 (16 warps). 128 rows/CTA; fused N=192 split 2 ways.
// cp.async double-buffered panels (fp16 sources; zero-convert fills).
#define QKV_BUF  (128*KSTR + 192*KSTR)
#define QKV_SMEM (2*QKV_BUF)
__global__ __launch_bounds__(512, 1) void qkv_tc()
{
    extern __shared__ __align__(16) char sm[];
    const int tid = threadIdx.x, w = tid >> 5, ln = tid & 31;
    const int m = ln & 3, qr = ln >> 2;
    const int wh = w >> 3;
    const int wrow = (w & 7) * 16;
    const int row0 = blockIdx.x * 128;
    const uint32_t SB = smem_u32(sm);

    const int l7 = ln & 7, l3 = (ln >> 3) & 1, l4 = (ln >> 4) & 1;
    const uint32_t offA = (uint32_t)((l7 + l3*8)*KSTR + l4*16);
    const uint32_t offB = (uint32_t)(l7*KSTR + (ln >> 3)*16);

    const __half* xp0 = g_xh + (size_t)row0 * CH;

    // fill panel c into buffer p
    #define QKV_FILL(c, p) do {                                              \
        uint32_t base = SB + (p)*QKV_BUF;                                    \
        const __half* xp = xp0 + (c)*64;                                     \
        _Pragma("unroll")                                                    \
        for (int i = 0; i < 2; i++) {                                        \
            int idx = tid + i*512, r = idx >> 3, c8 = idx & 7;               \
            CPA(base + (uint32_t)(r*KSTR + c8*16), xp + (size_t)r*CH + c8*8);\
        }                                                                    \
        const __half* wp = g_wt + (c)*64;                                    \
        _Pragma("unroll")                                                    \
        for (int i = 0; i < 3; i++) {                                        \
            int idx = tid + i*512, n = idx >> 3, c8 = idx & 7;               \
            CPA(base + (uint32_t)(128*KSTR + n*KSTR + c8*16),                \
                wp + (size_t)n*CH + c8*8);                                   \
        }                                                                    \
        CPA_COMMIT();                                                        \
    } while (0)

    float o[12][4];
    #pragma unroll
    for (int i = 0; i < 12; i++) { o[i][0]=o[i][1]=o[i][2]=o[i][3]=0.f; }

    QKV_FILL(0, 0);

    #pragma unroll 1
    for (int c = 0; c < 16; c++) {
        const int p = c & 1;
        CPA_WAIT0();
        __syncthreads();
        if (c < 15) QKV_FILL(c + 1, 1 - p);

        const uint32_t XB = SB + p*QKV_BUF;
        const uint32_t WBb = XB + 128*KSTR;
        #pragma unroll
        for (int ksh = 0; ksh < 2; ksh++) {
            uint32_t a[2][4];
            LDSM4(a[0][0], a[0][1], a[0][2], a[0][3],
                  XB + (uint32_t)(wrow*KSTR + ksh*64) + offA);
            LDSM4(a[1][0], a[1][1], a[1][2], a[1][3],
                  XB + (uint32_t)(wrow*KSTR + ksh*64 + 32) + offA);
            #pragma unroll
            for (int nt = 0; nt < 12; nt++) {
                uint32_t bf[4];
                LDSM4(bf[0], bf[1], bf[2], bf[3],
                      WBb + (uint32_t)((wh*96 + nt*8)*KSTR + ksh*64) + offB);
                mma16(o[nt], a[0], bf);
                mma16(o[nt], a[1], bf+2);
            }
        }
        __syncthreads();
    }
    __half* dsts[3] = {g_q, g_k, g_v};
    const int rg = row0 + wrow + qr;
    #pragma unroll
    for (int nt = 0; nt < 12; nt++) {
        int ntg = wh*96 + nt*8;
        __half* d = dsts[ntg >> 6];
        int col = (ntg & 63) + 2*m;
        *(__half2*)(d + (size_t)rg*HS + col) =
            __floats2half2_rn(o[nt][0], o[nt][1]);
        *(__half2*)(d + (size_t)(rg+8)*HS + col) =
            __floats2half2_rn(o[nt][2], o[nt][3]);
    }
}

// ----------------------------------------------------------- attention kernel
// grid 128 (4b x 32 qtiles of 128), block 512 = 2 groups x 256.
// Group g: key tiles jt = g, g+2, ... (split-K; no max subtraction => O,l
// purely additive). cp.async double-buffered K+V tiles per group.
#define TILE_BYTES (2*128*KSTR)                 // K + V
#define PS_BYTES   (16*PSTR)
#define ATT_SMEM   (4*TILE_BYTES + 16*PS_BYTES)
__global__ __launch_bounds__(512, 1) void attn_tc(float* __restrict__ out)
{
    extern __shared__ __align__(16) char sm[];
    const int tid = threadIdx.x, w = tid >> 5, ln = tid & 31;
    const int m = ln & 3, qr = ln >> 2;
    const int g = w >> 3;
    const int gtid = tid & 255;
    const int wrow = (w & 7) * 16;
    char* Psw = sm + 4*TILE_BYTES + w*PS_BYTES;
    const int b = blockIdx.x >> 5, qt = blockIdx.x & 31;
    const __half* qg = g_q + ((size_t)b*SEQ + qt*128) * HS;
    const __half* kg = g_k + (size_t)b*SEQ*HS;
    const __half* vg = g_v + (size_t)b*SEQ*HS;

    const int l7 = ln & 7, l3 = (ln >> 3) & 1, l4 = (ln >> 4) & 1;
    const uint32_t offA  = (uint32_t)((l7 + l3*8)*KSTR + l4*16);
    const uint32_t offKB = (uint32_t)(l7*KSTR + (ln >> 3)*16);
    const uint32_t offVB = (uint32_t)((l7 + l3*8)*KSTR + l4*16);
    const uint32_t offPA = (uint32_t)((l7 + l3*8)*PSTR + l4*16);
    const uint32_t SB = smem_u32(sm), PB = smem_u32(Psw);

    // fill tile jt into group-g buffer p (K then V), 8 cp.async per thread
    #define ATT_FILL(jt, p) do {                                             \
        uint32_t kb_ = SB + (uint32_t)((g*2 + (p))*TILE_BYTES);              \
        uint32_t vb_ = kb_ + 128*KSTR;                                       \
        const __half* kt_ = kg + (size_t)(jt)*128*HS;                        \
        const __half* vt_ = vg + (size_t)(jt)*128*HS;                        \
        _Pragma("unroll")                                                    \
        for (int i = 0; i < 4; i++) {                                        \
            int idx = gtid + i*256, r = idx >> 3, c8 = idx & 7;              \
            CPA(kb_ + (uint32_t)(r*KSTR + c8*16), kt_ + (size_t)r*HS + c8*8);\
            CPA(vb_ + (uint32_t)(r*KSTR + c8*16), vt_ + (size_t)r*HS + c8*8);\
        }                                                                    \
        CPA_COMMIT();                                                        \
    } while (0)

    // stage Q into first buffer region, pull frags, release
    #pragma unroll
    for (int i = 0; i < 2; i++) {
        int idx = tid + i*512, r = idx >> 3, c8 = idx & 7;
        *(uint4*)(sm + r*KSTR + c8*16) = *(const uint4*)(qg + (size_t)r*HS + c8*8);
    }
    __syncthreads();
    uint32_t q[4][4];
    {
        uint32_t qb = SB + (uint32_t)(wrow*KSTR) + offA;
        #pragma unroll
        for (int ks = 0; ks < 4; ks++)
            LDSM4(q[ks][0], q[ks][1], q[ks][2], q[ks][3], qb + ks*32);
    }
    __syncthreads();

    float o[8][4];
    #pragma unroll
    for (int nt = 0; nt < 8; nt++) { o[nt][0]=o[nt][1]=o[nt][2]=o[nt][3]=0.f; }
    float l0 = 0.f, l1 = 0.f;

    if (g <= qt) ATT_FILL(g, 0);
    int p = 0;

    #pragma unroll 1
    for (int jt = g; jt <= qt; jt += 2) {
        CPA_WAIT0();
        BARG(g+1);
        if (jt + 2 <= qt) ATT_FILL(jt + 2, 1 - p);

        const uint32_t KB = SB + (uint32_t)((g*2 + p)*TILE_BYTES);
        const uint32_t VB = KB + 128*KSTR;
        const bool diag = (jt == qt);
        const int rg0 = qt*128 + wrow + qr;
        const int rg1 = rg0 + 8;
        #pragma unroll 1
        for (int ch = 0; ch < 4; ch++) {
            float s[4][4];
            #pragma unroll
            for (int nt = 0; nt < 4; nt++)
                { s[nt][0]=s[nt][1]=s[nt][2]=s[nt][3]=0.f; }
            #pragma unroll
            for (int nt = 0; nt < 4; nt++) {
                const uint32_t krow = (uint32_t)((ch*32 + nt*8)*KSTR);
                uint32_t bf[4];
                LDSM4(bf[0], bf[1], bf[2], bf[3], KB + krow + offKB);
                mma16(s[nt], q[0], bf);
                mma16(s[nt], q[1], bf+2);
                LDSM4(bf[0], bf[1], bf[2], bf[3], KB + krow + 64 + offKB);
                mma16(s[nt], q[2], bf);
                mma16(s[nt], q[3], bf+2);
            }
            #pragma unroll
            for (int nt = 0; nt < 4; nt++) {
                const int kb = ch*32 + nt*8;
                const int kg0 = jt*128 + kb + 2*m;
                float p0 = ex2f(s[nt][0] * C_EXP);
                float p1 = ex2f(s[nt][1] * C_EXP);
                float p2 = ex2f(s[nt][2] * C_EXP);
                float p3 = ex2f(s[nt][3] * C_EXP);
                if (diag) {
                    if (kg0     > rg0) p0 = 0.f;
                    if (kg0 + 1 > rg0) p1 = 0.f;
                    if (kg0     > rg1) p2 = 0.f;
                    if (kg0 + 1 > rg1) p3 = 0.f;
                }
                l0 += p0 + p1;
                l1 += p2 + p3;
                *(uint32_t*)(Psw + qr*PSTR     + nt*16 + m*4) = packh2(p0, p1);
                *(uint32_t*)(Psw + (qr+8)*PSTR + nt*16 + m*4) = packh2(p2, p3);
            }
            __syncwarp();
            #pragma unroll
            for (int kst = 0; kst < 2; kst++) {
                uint32_t a[4];
                LDSM4(a[0], a[1], a[2], a[3], PB + (uint32_t)(kst*32) + offPA);
                const uint32_t vrow = (uint32_t)((ch*32 + kst*16)*KSTR);
                #pragma unroll
                for (int np = 0; np < 4; np++) {
                    uint32_t vb[4];
                    LDSM4T(vb[0], vb[1], vb[2], vb[3],
                           VB + vrow + (uint32_t)(np*32) + offVB);
                    mma16(o[2*np],   a, vb);
                    mma16(o[2*np+1], a, vb+2);
                }
            }
            __syncwarp();
        }
        BARG(g+1);
        p ^= 1;
    }

    // ---- combine the two split-K partials ----
    __syncthreads();
    l0 += __shfl_xor_sync(0xffffffffu, l0, 1);
    l0 += __shfl_xor_sync(0xffffffffu, l0, 2);
    l1 += __shfl_xor_sync(0xffffffffu, l1, 1);
    l1 += __shfl_xor_sync(0xffffffffu, l1, 2);

    float* Obuf = (float*)sm;            // [128][66]
    float* lbuf = (float*)sm + 128*66;   // [128]
    if (g == 0) {
        #pragma unroll
        for (int nt = 0; nt < 8; nt++) {
            *(float2*)&Obuf[(wrow+qr)*66 + nt*8 + 2*m]   = make_float2(o[nt][0], o[nt][1]);
            *(float2*)&Obuf[(wrow+qr+8)*66 + nt*8 + 2*m] = make_float2(o[nt][2], o[nt][3]);
        }
        if (m == 0) { lbuf[wrow+qr] = l0; lbuf[wrow+qr+8] = l1; }
    }
    __syncthreads();
    if (g == 1) {
        float inv0 = 1.f / (l0 + lbuf[wrow+qr]);
        float inv1 = 1.f / (l1 + lbuf[wrow+qr+8]);
        float* d = out + ((size_t)b*SEQ + qt*128 + wrow + qr) * HS;
        #pragma unroll
        for (int nt = 0; nt < 8; nt++) {
            float2 b0 = *(float2*)&Obuf[(wrow+qr)*66 + nt*8 + 2*m];
            float2 b1 = *(float2*)&Obuf[(wrow+qr+8)*66 + nt*8 + 2*m];
            *(float2*)(d + nt*8 + 2*m) =
                make_float2((o[nt][0]+b0.x)*inv0, (o[nt][1]+b0.y)*inv0);
            *(float2*)(d + (size_t)8*HS + nt*8 + 2*m) =
                make_float2((o[nt][2]+b1.x)*inv1, (o[nt][3]+b1.y)*inv1);
        }
    }
}

// ---------------------------------------------------------------------------
extern "C" void kernel_launch(void* const* d_in, const int* in_sizes, int n_in,
                              void* d_out, int out_size)
{
    const float* x  = (const float*)d_in[0];
    const float* Wq = (const float*)d_in[1];
    const float* Wk = (const float*)d_in[2];
    const float* Wv = (const float*)d_in[3];
    float* out = (float*)d_out;

    cudaFuncSetAttribute(qkv_tc,  cudaFuncAttributeMaxDynamicSharedMemorySize, QKV_SMEM);
    cudaFuncSetAttribute(attn_tc, cudaFuncAttributeMaxDynamicSharedMemorySize, ATT_SMEM);

    cvt_x<<<4096, 512>>>(x);
    cvt_w<<<384, 512>>>(Wq, Wk, Wv);
    qkv_tc<<<128, 512, QKV_SMEM>>>();
    attn_tc<<<128, 512, ATT_SMEM>>>(out);
}

// round 13
// speedup vs baseline: 2.2709x; 1.0401x over previous
#include <cuda_runtime.h>
#include <cuda_fp16.h>
#include <cstdint>

#define BATCH 4
#define SEQ   4096
#define CH    1024
#define HS    64

__device__ __half g_q[BATCH*SEQ*HS];
__device__ __half g_k[BATCH*SEQ*HS];
__device__ __half g_v[BATCH*SEQ*HS];
__device__ __half g_xh[BATCH*SEQ*CH];        // x pre-converted to fp16
__device__ __half g_wt[3*HS*CH];             // W transposed: [n=192][k=1024] fp16
__device__ float  g_Opart[BATCH*SEQ*HS];     // attention partial O (summed via RED)
__device__ float  g_lpart[BATCH*SEQ];        // attention partial l

// ---------------------------------------------------------------- primitives
__device__ __forceinline__ uint32_t smem_u32(const void* p){
    uint32_t a;
    asm("{ .reg .u64 t; cvta.to.shared.u64 t, %1; cvt.u32.u64 %0, t; }":"=r"(a):"l"(p));
    return a;
}
__device__ __forceinline__ float ex2f(float x){
    float y; asm("ex2.approx.ftz.f32 %0, %1;" : "=f"(y) : "f"(x)); return y;
}
__device__ __forceinline__ uint32_t packh2(float lo, float hi){
    uint32_t u;
    asm("cvt.rn.f16x2.f32 %0, %2, %1;" : "=r"(u) : "f"(lo), "f"(hi));
    return u;
}
__device__ __forceinline__ void mma16(float* d, const uint32_t* a, const uint32_t* b){
    asm volatile("mma.sync.aligned.m16n8k16.row.col.f32.f16.f16.f32 "
        "{%0,%1,%2,%3}, {%4,%5,%6,%7}, {%8,%9}, {%0,%1,%2,%3};"
        : "+f"(d[0]), "+f"(d[1]), "+f"(d[2]), "+f"(d[3])
        : "r"(a[0]), "r"(a[1]), "r"(a[2]), "r"(a[3]), "r"(b[0]), "r"(b[1]));
}
#define LDSM4(r0,r1,r2,r3,addr)                                              \
    asm volatile("ldmatrix.sync.aligned.m8n8.x4.shared.b16 {%0,%1,%2,%3}, [%4];" \
        : "=r"(r0), "=r"(r1), "=r"(r2), "=r"(r3) : "r"(addr))
#define LDSM4T(r0,r1,r2,r3,addr)                                             \
    asm volatile("ldmatrix.sync.aligned.m8n8.x4.trans.shared.b16 {%0,%1,%2,%3}, [%4];" \
        : "=r"(r0), "=r"(r1), "=r"(r2), "=r"(r3) : "r"(addr))
#define CPA(dst, src) asm volatile("cp.async.cg.shared.global [%0], [%1], 16;" \
        :: "r"(dst), "l"(src) : "memory")
#define CPA_COMMIT() asm volatile("cp.async.commit_group;" ::: "memory")
#define CPA_WAIT0()  asm volatile("cp.async.wait_group 0;" ::: "memory")

#define BARG(id) asm volatile("bar.sync %0, 256;" :: "r"(id) : "memory")
#define C_EXP 0.18033688011112042f   // (1/8) * log2(e)

#define KSTR 144    // fp16 tile row stride (bytes) = 9*16 (ldmatrix-aligned)
#define PSTR 80     // P buffer row stride = 5*16

// ------------------------------------------------------------ small kernels
__global__ __launch_bounds__(512) void zero_part(){
    int i = blockIdx.x * 512 + threadIdx.x;          // 266240 float4
    if (i < 262144) ((float4*)g_Opart)[i] = make_float4(0.f,0.f,0.f,0.f);
    else ((float4*)g_lpart)[i - 262144] = make_float4(0.f,0.f,0.f,0.f);
}
__global__ __launch_bounds__(512) void cvt_x(const float* __restrict__ x){
    size_t i = ((size_t)blockIdx.x * 512 + threadIdx.x) * 8;
    float4 a = *(const float4*)(x + i);
    float4 b = *(const float4*)(x + i + 4);
    uint4 u = make_uint4(packh2(a.x, a.y), packh2(a.z, a.w),
                         packh2(b.x, b.y), packh2(b.z, b.w));
    *(uint4*)(g_xh + i) = u;
}
__global__ __launch_bounds__(512) void cvt_w(const float* __restrict__ Wq,
                                             const float* __restrict__ Wk,
                                             const float* __restrict__ Wv){
    int idx = blockIdx.x * 512 + threadIdx.x;       // 3*65536 total
    int w = idx >> 16, rem = idx & 65535;
    int k = rem >> 6, n = rem & 63;
    const float* W = (w == 0) ? Wq : (w == 1) ? Wk : Wv;
    g_wt[(size_t)(w*64 + n)*CH + k] = __float2half(W[rem]);
}
__global__ __launch_bounds__(512) void attn_epi(float* __restrict__ out){
    int i = blockIdx.x * 512 + threadIdx.x;          // 262144 float4
    float4 o = ((float4*)g_Opart)[i];
    float inv = 1.f / g_lpart[i >> 4];
    ((float4*)out)[i] = make_float4(o.x*inv, o.y*inv, o.z*inv, o.w*inv);
}

// ---------------------------------------------------------------- QKV kernel
// (unchanged from round 12) grid 128, block 512; cp.async double-buffered.
#define QKV_BUF  (128*KSTR + 192*KSTR)
#define QKV_SMEM (2*QKV_BUF)
__global__ __launch_bounds__(512, 1) void qkv_tc()
{
    extern __shared__ __align__(16) char sm[];
    const int tid = threadIdx.x, w = tid >> 5, ln = tid & 31;
    const int m = ln & 3, qr = ln >> 2;
    const int wh = w >> 3;
    const int wrow = (w & 7) * 16;
    const int row0 = blockIdx.x * 128;
    const uint32_t SB = smem_u32(sm);

    const int l7 = ln & 7, l3 = (ln >> 3) & 1, l4 = (ln >> 4) & 1;
    const uint32_t offA = (uint32_t)((l7 + l3*8)*KSTR + l4*16);
    const uint32_t offB = (uint32_t)(l7*KSTR + (ln >> 3)*16);

    const __half* xp0 = g_xh + (size_t)row0 * CH;

    #define QKV_FILL(c, p) do {                                              \
        uint32_t base = SB + (p)*QKV_BUF;                                    \
        const __half* xp = xp0 + (c)*64;                                     \
        _Pragma("unroll")                                                    \
        for (int i = 0; i < 2; i++) {                                        \
            int idx = tid + i*512, r = idx >> 3, c8 = idx & 7;               \
            CPA(base + (uint32_t)(r*KSTR + c8*16), xp + (size_t)r*CH + c8*8);\
        }                                                                    \
        const __half* wp = g_wt + (c)*64;                                    \
        _Pragma("unroll")                                                    \
        for (int i = 0; i < 3; i++) {                                        \
            int idx = tid + i*512, n = idx >> 3, c8 = idx & 7;               \
            CPA(base + (uint32_t)(128*KSTR + n*KSTR + c8*16),                \
                wp + (size_t)n*CH + c8*8);                                   \
        }                                                                    \
        CPA_COMMIT();                                                        \
    } while (0)

    float o[12][4];
    #pragma unroll
    for (int i = 0; i < 12; i++) { o[i][0]=o[i][1]=o[i][2]=o[i][3]=0.f; }

    QKV_FILL(0, 0);

    #pragma unroll 1
    for (int c = 0; c < 16; c++) {
        const int p = c & 1;
        CPA_WAIT0();
        __syncthreads();
        if (c < 15) QKV_FILL(c + 1, 1 - p);

        const uint32_t XB = SB + p*QKV_BUF;
        const uint32_t WBb = XB + 128*KSTR;
        #pragma unroll
        for (int ksh = 0; ksh < 2; ksh++) {
            uint32_t a[2][4];
            LDSM4(a[0][0], a[0][1], a[0][2], a[0][3],
                  XB + (uint32_t)(wrow*KSTR + ksh*64) + offA);
            LDSM4(a[1][0], a[1][1], a[1][2], a[1][3],
                  XB + (uint32_t)(wrow*KSTR + ksh*64 + 32) + offA);
            #pragma unroll
            for (int nt = 0; nt < 12; nt++) {
                uint32_t bf[4];
                LDSM4(bf[0], bf[1], bf[2], bf[3],
                      WBb + (uint32_t)((wh*96 + nt*8)*KSTR + ksh*64) + offB);
                mma16(o[nt], a[0], bf);
                mma16(o[nt], a[1], bf+2);
            }
        }
        __syncthreads();
    }
    __half* dsts[3] = {g_q, g_k, g_v};
    const int rg = row0 + wrow + qr;
    #pragma unroll
    for (int nt = 0; nt < 12; nt++) {
        int ntg = wh*96 + nt*8;
        __half* d = dsts[ntg >> 6];
        int col = (ntg & 63) + 2*m;
        *(__half2*)(d + (size_t)rg*HS + col) =
            __floats2half2_rn(o[nt][0], o[nt][1]);
        *(__half2*)(d + (size_t)(rg+8)*HS + col) =
            __floats2half2_rn(o[nt][2], o[nt][3]);
    }
}

// ----------------------------------------------------------- attention kernel
// Balanced flat schedule: 2112 (b,qt,jt) units split contiguously over 148
// CTAs (~14 each). Per segment: stage Q, two 256-thread groups take alternate
// jt (split-K additive; no max subtraction), then RED-flush partial O,l to
// global scratch. attn_epi divides. K/V cp.async double-buffered per group.
#define TILE_BYTES (2*128*KSTR)                 // K + V
#define QS_BYTES   (128*KSTR)
#define PS_BYTES   (16*PSTR)
#define ATT_SMEM   (QS_BYTES + 4*TILE_BYTES + 16*PS_BYTES)
#define NUNITS 2112
#define NCTA   148
__global__ __launch_bounds__(512, 1) void attn_tc()
{
    extern __shared__ __align__(16) char sm[];
    const int tid = threadIdx.x, w = tid >> 5, ln = tid & 31;
    const int m = ln & 3, qr = ln >> 2;
    const int g = w >> 3;
    const int gtid = tid & 255;
    const int wrow = (w & 7) * 16;
    char* Psw = sm + QS_BYTES + 4*TILE_BYTES + w*PS_BYTES;

    const int l7 = ln & 7, l3 = (ln >> 3) & 1, l4 = (ln >> 4) & 1;
    const uint32_t offA  = (uint32_t)((l7 + l3*8)*KSTR + l4*16);
    const uint32_t offKB = (uint32_t)(l7*KSTR + (ln >> 3)*16);
    const uint32_t offVB = (uint32_t)((l7 + l3*8)*KSTR + l4*16);
    const uint32_t offPA = (uint32_t)((l7 + l3*8)*PSTR + l4*16);
    const uint32_t SB = smem_u32(sm), PB = smem_u32(Psw);

    // contiguous unit range for this CTA: 2112 = 148*14 + 40
    const int bi = blockIdx.x;
    int u  = bi*14 + (bi < 40 ? bi : 40);
    const int u1 = u + 14 + (bi < 40 ? 1 : 0);

    #define ATT_FILL(jt, p) do {                                             \
        uint32_t kb_ = SB + QS_BYTES + (uint32_t)((g*2 + (p))*TILE_BYTES);   \
        uint32_t vb_ = kb_ + 128*KSTR;                                       \
        const __half* kt_ = kg + (size_t)(jt)*128*HS;                        \
        const __half* vt_ = vg + (size_t)(jt)*128*HS;                        \
        _Pragma("unroll")                                                    \
        for (int i = 0; i < 4; i++) {                                        \
            int idx = gtid + i*256, r = idx >> 3, c8 = idx & 7;              \
            CPA(kb_ + (uint32_t)(r*KSTR + c8*16), kt_ + (size_t)r*HS + c8*8);\
            CPA(vb_ + (uint32_t)(r*KSTR + c8*16), vt_ + (size_t)r*HS + c8*8);\
        }                                                                    \
        CPA_COMMIT();                                                        \
    } while (0)

    #pragma unroll 1
    while (u < u1) {
        // decode (b, qt, jt0) and segment extent
        const int bb = u / 528;
        const int r  = u - bb * 528;
        int qt = (int)((sqrtf(8.f*r + 1.f) - 1.f) * 0.5f);
        while ((qt+1)*(qt+2)/2 <= r) qt++;
        while (qt*(qt+1)/2 > r) qt--;
        const int jt0 = r - qt*(qt+1)/2;
        int take = qt + 1 - jt0;
        if (take > u1 - u) take = u1 - u;

        const __half* qg = g_q + ((size_t)bb*SEQ + qt*128) * HS;
        const __half* kg = g_k + (size_t)bb*SEQ*HS;
        const __half* vg = g_v + (size_t)bb*SEQ*HS;

        // stage Q (everyone done with previous segment's QS reads)
        __syncthreads();
        #pragma unroll
        for (int i = 0; i < 2; i++) {
            int idx = tid + i*512, rr = idx >> 3, c8 = idx & 7;
            *(uint4*)(sm + rr*KSTR + c8*16) = *(const uint4*)(qg + (size_t)rr*HS + c8*8);
        }
        __syncthreads();
        uint32_t q[4][4];
        {
            uint32_t qb = SB + (uint32_t)(wrow*KSTR) + offA;
            #pragma unroll
            for (int ks = 0; ks < 4; ks++)
                LDSM4(q[ks][0], q[ks][1], q[ks][2], q[ks][3], qb + ks*32);
        }

        float o[8][4];
        #pragma unroll
        for (int nt = 0; nt < 8; nt++) { o[nt][0]=o[nt][1]=o[nt][2]=o[nt][3]=0.f; }
        float l0 = 0.f, l1 = 0.f;

        const int myfirst = jt0 + g;
        const int myend   = jt0 + take;
        if (myfirst < myend) ATT_FILL(myfirst, 0);
        int p = 0;

        #pragma unroll 1
        for (int jt = myfirst; jt < myend; jt += 2) {
            CPA_WAIT0();
            BARG(g+1);
            if (jt + 2 < myend) ATT_FILL(jt + 2, 1 - p);

            const uint32_t KB = SB + QS_BYTES + (uint32_t)((g*2 + p)*TILE_BYTES);
            const uint32_t VB = KB + 128*KSTR;
            const bool diag = (jt == qt);
            const int rg0 = qt*128 + wrow + qr;
            const int rg1 = rg0 + 8;
            #pragma unroll 1
            for (int ch = 0; ch < 4; ch++) {
                float s[4][4];
                #pragma unroll
                for (int nt = 0; nt < 4; nt++)
                    { s[nt][0]=s[nt][1]=s[nt][2]=s[nt][3]=0.f; }
                #pragma unroll
                for (int nt = 0; nt < 4; nt++) {
                    const uint32_t krow = (uint32_t)((ch*32 + nt*8)*KSTR);
                    uint32_t bf[4];
                    LDSM4(bf[0], bf[1], bf[2], bf[3], KB + krow + offKB);
                    mma16(s[nt], q[0], bf);
                    mma16(s[nt], q[1], bf+2);
                    LDSM4(bf[0], bf[1], bf[2], bf[3], KB + krow + 64 + offKB);
                    mma16(s[nt], q[2], bf);
                    mma16(s[nt], q[3], bf+2);
                }
                #pragma unroll
                for (int nt = 0; nt < 4; nt++) {
                    const int kb = ch*32 + nt*8;
                    const int kg0 = jt*128 + kb + 2*m;
                    float p0 = ex2f(s[nt][0] * C_EXP);
                    float p1 = ex2f(s[nt][1] * C_EXP);
                    float p2 = ex2f(s[nt][2] * C_EXP);
                    float p3 = ex2f(s[nt][3] * C_EXP);
                    if (diag) {
                        if (kg0     > rg0) p0 = 0.f;
                        if (kg0 + 1 > rg0) p1 = 0.f;
                        if (kg0     > rg1) p2 = 0.f;
                        if (kg0 + 1 > rg1) p3 = 0.f;
                    }
                    l0 += p0 + p1;
                    l1 += p2 + p3;
                    *(uint32_t*)(Psw + qr*PSTR     + nt*16 + m*4) = packh2(p0, p1);
                    *(uint32_t*)(Psw + (qr+8)*PSTR + nt*16 + m*4) = packh2(p2, p3);
                }
                __syncwarp();
                #pragma unroll
                for (int kst = 0; kst < 2; kst++) {
                    uint32_t a[4];
                    LDSM4(a[0], a[1], a[2], a[3], PB + (uint32_t)(kst*32) + offPA);
                    const uint32_t vrow = (uint32_t)((ch*32 + kst*16)*KSTR);
                    #pragma unroll
                    for (int np = 0; np < 4; np++) {
                        uint32_t vb[4];
                        LDSM4T(vb[0], vb[1], vb[2], vb[3],
                               VB + vrow + (uint32_t)(np*32) + offVB);
                        mma16(o[2*np],   a, vb);
                        mma16(o[2*np+1], a, vb+2);
                    }
                }
                __syncwarp();
            }
            BARG(g+1);
            p ^= 1;
        }

        // flush partial (O, l) for this segment via RED adds
        if (myfirst < myend) {
            l0 += __shfl_xor_sync(0xffffffffu, l0, 1);
            l0 += __shfl_xor_sync(0xffffffffu, l0, 2);
            l1 += __shfl_xor_sync(0xffffffffu, l1, 1);
            l1 += __shfl_xor_sync(0xffffffffu, l1, 2);
            float* Ob = g_Opart + ((size_t)(bb*32 + qt)*128) * 64;
            const int r0 = wrow + qr, r1 = r0 + 8;
            #pragma unroll
            for (int nt = 0; nt < 8; nt++) {
                int col = nt*8 + 2*m;
                atomicAdd(&Ob[r0*64 + col],     o[nt][0]);
                atomicAdd(&Ob[r0*64 + col + 1], o[nt][1]);
                atomicAdd(&Ob[r1*64 + col],     o[nt][2]);
                atomicAdd(&Ob[r1*64 + col + 1], o[nt][3]);
            }
            if (m == 0) {
                atomicAdd(&g_lpart[(bb*32 + qt)*128 + r0], l0);
                atomicAdd(&g_lpart[(bb*32 + qt)*128 + r1], l1);
            }
        }
        u += take;
    }
}

// ---------------------------------------------------------------------------
extern "C" void kernel_launch(void* const* d_in, const int* in_sizes, int n_in,
                              void* d_out, int out_size)
{
    const float* x  = (const float*)d_in[0];
    const float* Wq = (const float*)d_in[1];
    const float* Wk = (const float*)d_in[2];
    const float* Wv = (const float*)d_in[3];
    float* out = (float*)d_out;

    cudaFuncSetAttribute(qkv_tc,  cudaFuncAttributeMaxDynamicSharedMemorySize, QKV_SMEM);
    cudaFuncSetAttribute(attn_tc, cudaFuncAttributeMaxDynamicSharedMemorySize, ATT_SMEM);

    zero_part<<<520, 512>>>();
    cvt_x<<<4096, 512>>>(x);
    cvt_w<<<384, 512>>>(Wq, Wk, Wv);
    qkv_tc<<<128, 512, QKV_SMEM>>>();
    attn_tc<<<NCTA, 512, ATT_SMEM>>>();
    attn_epi<<<512, 512>>>(out);
}

// round 14
// speedup vs baseline: 2.4080x; 1.0604x over previous
#include <cuda_runtime.h>
#include <cuda_fp16.h>
#include <cstdint>

#define BATCH 4
#define SEQ   4096
#define CH    1024
#define HS    64

__device__ __half g_q[BATCH*SEQ*HS];
__device__ __half g_k[BATCH*SEQ*HS];
__device__ __half g_v[BATCH*SEQ*HS];
__device__ __half g_wt[3*HS*CH];             // W transposed: [n=192][k=1024] fp16
__device__ float  g_Opart[BATCH*SEQ*HS];     // attention partial O (summed via RED)
__device__ float  g_lpart[BATCH*SEQ];        // attention partial l

// ---------------------------------------------------------------- primitives
__device__ __forceinline__ uint32_t smem_u32(const void* p){
    uint32_t a;
    asm("{ .reg .u64 t; cvta.to.shared.u64 t, %1; cvt.u32.u64 %0, t; }":"=r"(a):"l"(p));
    return a;
}
__device__ __forceinline__ float ex2f(float x){
    float y; asm("ex2.approx.ftz.f32 %0, %1;" : "=f"(y) : "f"(x)); return y;
}
__device__ __forceinline__ uint32_t packh2(float lo, float hi){
    uint32_t u;
    asm("cvt.rn.f16x2.f32 %0, %2, %1;" : "=r"(u) : "f"(lo), "f"(hi));
    return u;
}
__device__ __forceinline__ void mma16(float* d, const uint32_t* a, const uint32_t* b){
    asm volatile("mma.sync.aligned.m16n8k16.row.col.f32.f16.f16.f32 "
        "{%0,%1,%2,%3}, {%4,%5,%6,%7}, {%8,%9}, {%0,%1,%2,%3};"
        : "+f"(d[0]), "+f"(d[1]), "+f"(d[2]), "+f"(d[3])
        : "r"(a[0]), "r"(a[1]), "r"(a[2]), "r"(a[3]), "r"(b[0]), "r"(b[1]));
}
#define LDSM4(r0,r1,r2,r3,addr)                                              \
    asm volatile("ldmatrix.sync.aligned.m8n8.x4.shared.b16 {%0,%1,%2,%3}, [%4];" \
        : "=r"(r0), "=r"(r1), "=r"(r2), "=r"(r3) : "r"(addr))
#define LDSM4T(r0,r1,r2,r3,addr)                                             \
    asm volatile("ldmatrix.sync.aligned.m8n8.x4.trans.shared.b16 {%0,%1,%2,%3}, [%4];" \
        : "=r"(r0), "=r"(r1), "=r"(r2), "=r"(r3) : "r"(addr))
#define CPA(dst, src) asm volatile("cp.async.cg.shared.global [%0], [%1], 16;" \
        :: "r"(dst), "l"(src) : "memory")
#define CPA_COMMIT() asm volatile("cp.async.commit_group;" ::: "memory")
#define CPA_WAIT0()  asm volatile("cp.async.wait_group 0;" ::: "memory")

#define BARG(id) asm volatile("bar.sync %0, 256;" :: "r"(id) : "memory")
#define C_EXP 0.18033688011112042f   // (1/8) * log2(e)

#define KSTR 144    // fp16 tile row stride (bytes) = 9*16 (ldmatrix-aligned)
#define PSTR 80     // P buffer row stride = 5*16
#define XSTG 272    // f32 staging row stride (bytes) = 17*16

// ------------------------------------------------------------ prep kernel
// zeroes partial buffers + converts W (transposed) to fp16, one launch.
__global__ __launch_bounds__(512) void prep(const float* __restrict__ Wq,
                                            const float* __restrict__ Wk,
                                            const float* __restrict__ Wv){
    int idx = blockIdx.x * 512 + threadIdx.x;        // grid 520*512 = 266240
    if (idx < 262144) ((float4*)g_Opart)[idx] = make_float4(0.f,0.f,0.f,0.f);
    else ((float4*)g_lpart)[idx - 262144] = make_float4(0.f,0.f,0.f,0.f);
    if (idx < 3*65536) {
        int w = idx >> 16, rem = idx & 65535;
        int k = rem >> 6, n = rem & 63;
        const float* W = (w == 0) ? Wq : (w == 1) ? Wk : Wv;
        g_wt[(size_t)(w*64 + n)*CH + k] = __float2half(W[rem]);
    }
}
__global__ __launch_bounds__(512) void attn_epi(float* __restrict__ out){
    int i = blockIdx.x * 512 + threadIdx.x;          // 262144 float4
    float4 o = ((float4*)g_Opart)[i];
    float inv = 1.f / g_lpart[i >> 4];
    ((float4*)out)[i] = make_float4(o.x*inv, o.y*inv, o.z*inv, o.w*inv);
}

// ---------------------------------------------------------------- QKV kernel
// grid 128, block 512. cp.async double-buffered: f32 x panel -> staging,
// in-kernel convert to fp16 tile; W panels cp.async fp16 from g_wt.
#define QKV_BUF  (128*XSTG + 128*KSTR + 192*KSTR)
#define QKV_SMEM (2*QKV_BUF)
__global__ __launch_bounds__(512, 1) void qkv_tc(const float* __restrict__ x)
{
    extern __shared__ __align__(16) char sm[];
    const int tid = threadIdx.x, w = tid >> 5, ln = tid & 31;
    const int m = ln & 3, qr = ln >> 2;
    const int wh = w >> 3;
    const int wrow = (w & 7) * 16;
    const int row0 = blockIdx.x * 128;
    const uint32_t SB = smem_u32(sm);

    const int l7 = ln & 7, l3 = (ln >> 3) & 1, l4 = (ln >> 4) & 1;
    const uint32_t offA = (uint32_t)((l7 + l3*8)*KSTR + l4*16);
    const uint32_t offB = (uint32_t)(l7*KSTR + (ln >> 3)*16);

    const float* xp0 = x + (size_t)row0 * CH;

    // fill panel c into buffer p: x as f32 into staging, W fp16 direct
    #define QKV_FILL(c, p) do {                                              \
        uint32_t base = SB + (p)*QKV_BUF;                                    \
        const float* xp = xp0 + (c)*64;                                      \
        _Pragma("unroll")                                                    \
        for (int i = 0; i < 4; i++) {                                        \
            int idx = tid + i*512, r = idx >> 4, c16 = idx & 15;             \
            CPA(base + (uint32_t)(r*XSTG + c16*16), xp + (size_t)r*CH + c16*4);\
        }                                                                    \
        const __half* wp = g_wt + (c)*64;                                    \
        _Pragma("unroll")                                                    \
        for (int i = 0; i < 3; i++) {                                        \
            int idx = tid + i*512, n = idx >> 3, c8 = idx & 7;               \
            CPA(base + (uint32_t)(128*XSTG + 128*KSTR + n*KSTR + c8*16),     \
                wp + (size_t)n*CH + c8*8);                                   \
        }                                                                    \
        CPA_COMMIT();                                                        \
    } while (0)

    float o[12][4];
    #pragma unroll
    for (int i = 0; i < 12; i++) { o[i][0]=o[i][1]=o[i][2]=o[i][3]=0.f; }

    QKV_FILL(0, 0);

    const int cr = tid >> 2, cs = tid & 3;   // convert mapping: row, 16-el segment

    #pragma unroll 1
    for (int c = 0; c < 16; c++) {
        const int p = c & 1;
        CPA_WAIT0();
        __syncthreads();
        if (c < 15) QKV_FILL(c + 1, 1 - p);

        // convert staged f32 panel -> fp16 tile
        {
            const char* stg = sm + p*QKV_BUF;
            char* xt = sm + p*QKV_BUF + 128*XSTG;
            float4 f0 = *(const float4*)(stg + cr*XSTG + cs*64);
            float4 f1 = *(const float4*)(stg + cr*XSTG + cs*64 + 16);
            float4 f2 = *(const float4*)(stg + cr*XSTG + cs*64 + 32);
            float4 f3 = *(const float4*)(stg + cr*XSTG + cs*64 + 48);
            uint4 u0 = make_uint4(packh2(f0.x,f0.y), packh2(f0.z,f0.w),
                                  packh2(f1.x,f1.y), packh2(f1.z,f1.w));
            uint4 u1 = make_uint4(packh2(f2.x,f2.y), packh2(f2.z,f2.w),
                                  packh2(f3.x,f3.y), packh2(f3.z,f3.w));
            *(uint4*)(xt + cr*KSTR + cs*32)      = u0;
            *(uint4*)(xt + cr*KSTR + cs*32 + 16) = u1;
        }
        __syncthreads();

        const uint32_t XB  = SB + p*QKV_BUF + 128*XSTG;
        const uint32_t WBb = XB + 128*KSTR;
        #pragma unroll
        for (int ksh = 0; ksh < 2; ksh++) {
            uint32_t a[2][4];
            LDSM4(a[0][0], a[0][1], a[0][2], a[0][3],
                  XB + (uint32_t)(wrow*KSTR + ksh*64) + offA);
            LDSM4(a[1][0], a[1][1], a[1][2], a[1][3],
                  XB + (uint32_t)(wrow*KSTR + ksh*64 + 32) + offA);
            #pragma unroll
            for (int nt = 0; nt < 12; nt++) {
                uint32_t bf[4];
                LDSM4(bf[0], bf[1], bf[2], bf[3],
                      WBb + (uint32_t)((wh*96 + nt*8)*KSTR + ksh*64) + offB);
                mma16(o[nt], a[0], bf);
                mma16(o[nt], a[1], bf+2);
            }
        }
    }
    __half* dsts[3] = {g_q, g_k, g_v};
    const int rg = row0 + wrow + qr;
    #pragma unroll
    for (int nt = 0; nt < 12; nt++) {
        int ntg = wh*96 + nt*8;
        __half* d = dsts[ntg >> 6];
        int col = (ntg & 63) + 2*m;
        *(__half2*)(d + (size_t)rg*HS + col) =
            __floats2half2_rn(o[nt][0], o[nt][1]);
        *(__half2*)(d + (size_t)(rg+8)*HS + col) =
            __floats2half2_rn(o[nt][2], o[nt][3]);
    }
}

// ----------------------------------------------------------- attention kernel
// (unchanged from round 13) Balanced flat schedule over 148 CTAs; split-K
// additive partials flushed via RED; cp.async double-buffered K+V per group.
#define TILE_BYTES (2*128*KSTR)                 // K + V
#define QS_BYTES   (128*KSTR)
#define PS_BYTES   (16*PSTR)
#define ATT_SMEM   (QS_BYTES + 4*TILE_BYTES + 16*PS_BYTES)
#define NCTA   148
__global__ __launch_bounds__(512, 1) void attn_tc()
{
    extern __shared__ __align__(16) char sm[];
    const int tid = threadIdx.x, w = tid >> 5, ln = tid & 31;
    const int m = ln & 3, qr = ln >> 2;
    const int g = w >> 3;
    const int gtid = tid & 255;
    const int wrow = (w & 7) * 16;
    char* Psw = sm + QS_BYTES + 4*TILE_BYTES + w*PS_BYTES;

    const int l7 = ln & 7, l3 = (ln >> 3) & 1, l4 = (ln >> 4) & 1;
    const uint32_t offA  = (uint32_t)((l7 + l3*8)*KSTR + l4*16);
    const uint32_t offKB = (uint32_t)(l7*KSTR + (ln >> 3)*16);
    const uint32_t offVB = (uint32_t)((l7 + l3*8)*KSTR + l4*16);
    const uint32_t offPA = (uint32_t)((l7 + l3*8)*PSTR + l4*16);
    const uint32_t SB = smem_u32(sm), PB = smem_u32(Psw);

    const int bi = blockIdx.x;
    int u  = bi*14 + (bi < 40 ? bi : 40);
    const int u1 = u + 14 + (bi < 40 ? 1 : 0);

    #define ATT_FILL(jt, p) do {                                             \
        uint32_t kb_ = SB + QS_BYTES + (uint32_t)((g*2 + (p))*TILE_BYTES);   \
        uint32_t vb_ = kb_ + 128*KSTR;                                       \
        const __half* kt_ = kg + (size_t)(jt)*128*HS;                        \
        const __half* vt_ = vg + (size_t)(jt)*128*HS;                        \
        _Pragma("unroll")                                                    \
        for (int i = 0; i < 4; i++) {                                        \
            int idx = gtid + i*256, r = idx >> 3, c8 = idx & 7;              \
            CPA(kb_ + (uint32_t)(r*KSTR + c8*16), kt_ + (size_t)r*HS + c8*8);\
            CPA(vb_ + (uint32_t)(r*KSTR + c8*16), vt_ + (size_t)r*HS + c8*8);\
        }                                                                    \
        CPA_COMMIT();                                                        \
    } while (0)

    #pragma unroll 1
    while (u < u1) {
        const int bb = u / 528;
        const int r  = u - bb * 528;
        int qt = (int)((sqrtf(8.f*r + 1.f) - 1.f) * 0.5f);
        while ((qt+1)*(qt+2)/2 <= r) qt++;
        while (qt*(qt+1)/2 > r) qt--;
        const int jt0 = r - qt*(qt+1)/2;
        int take = qt + 1 - jt0;
        if (take > u1 - u) take = u1 - u;

        const __half* qg = g_q + ((size_t)bb*SEQ + qt*128) * HS;
        const __half* kg = g_k + (size_t)bb*SEQ*HS;
        const __half* vg = g_v + (size_t)bb*SEQ*HS;

        __syncthreads();
        #pragma unroll
        for (int i = 0; i < 2; i++) {
            int idx = tid + i*512, rr = idx >> 3, c8 = idx & 7;
            *(uint4*)(sm + rr*KSTR + c8*16) = *(const uint4*)(qg + (size_t)rr*HS + c8*8);
        }
        __syncthreads();
        uint32_t q[4][4];
        {
            uint32_t qb = SB + (uint32_t)(wrow*KSTR) + offA;
            #pragma unroll
            for (int ks = 0; ks < 4; ks++)
                LDSM4(q[ks][0], q[ks][1], q[ks][2], q[ks][3], qb + ks*32);
        }

        float o[8][4];
        #pragma unroll
        for (int nt = 0; nt < 8; nt++) { o[nt][0]=o[nt][1]=o[nt][2]=o[nt][3]=0.f; }
        float l0 = 0.f, l1 = 0.f;

        const int myfirst = jt0 + g;
        const int myend   = jt0 + take;
        if (myfirst < myend) ATT_FILL(myfirst, 0);
        int p = 0;

        #pragma unroll 1
        for (int jt = myfirst; jt < myend; jt += 2) {
            CPA_WAIT0();
            BARG(g+1);
            if (jt + 2 < myend) ATT_FILL(jt + 2, 1 - p);

            const uint32_t KB = SB + QS_BYTES + (uint32_t)((g*2 + p)*TILE_BYTES);
            const uint32_t VB = KB + 128*KSTR;
            const bool diag = (jt == qt);
            const int rg0 = qt*128 + wrow + qr;
            const int rg1 = rg0 + 8;
            #pragma unroll 1
            for (int ch = 0; ch < 4; ch++) {
                float s[4][4];
                #pragma unroll
                for (int nt = 0; nt < 4; nt++)
                    { s[nt][0]=s[nt][1]=s[nt][2]=s[nt][3]=0.f; }
                #pragma unroll
                for (int nt = 0; nt < 4; nt++) {
                    const uint32_t krow = (uint32_t)((ch*32 + nt*8)*KSTR);
                    uint32_t bf[4];
                    LDSM4(bf[0], bf[1], bf[2], bf[3], KB + krow + offKB);
                    mma16(s[nt], q[0], bf);
                    mma16(s[nt], q[1], bf+2);
                    LDSM4(bf[0], bf[1], bf[2], bf[3], KB + krow + 64 + offKB);
                    mma16(s[nt], q[2], bf);
                    mma16(s[nt], q[3], bf+2);
                }
                #pragma unroll
                for (int nt = 0; nt < 4; nt++) {
                    const int kb = ch*32 + nt*8;
                    const int kg0 = jt*128 + kb + 2*m;
                    float p0 = ex2f(s[nt][0] * C_EXP);
                    float p1 = ex2f(s[nt][1] * C_EXP);
                    float p2 = ex2f(s[nt][2] * C_EXP);
                    float p3 = ex2f(s[nt][3] * C_EXP);
                    if (diag) {
                        if (kg0     > rg0) p0 = 0.f;
                        if (kg0 + 1 > rg0) p1 = 0.f;
                        if (kg0     > rg1) p2 = 0.f;
                        if (kg0 + 1 > rg1) p3 = 0.f;
                    }
                    l0 += p0 + p1;
                    l1 += p2 + p3;
                    *(uint32_t*)(Psw + qr*PSTR     + nt*16 + m*4) = packh2(p0, p1);
                    *(uint32_t*)(Psw + (qr+8)*PSTR + nt*16 + m*4) = packh2(p2, p3);
                }
                __syncwarp();
                #pragma unroll
                for (int kst = 0; kst < 2; kst++) {
                    uint32_t a[4];
                    LDSM4(a[0], a[1], a[2], a[3], PB + (uint32_t)(kst*32) + offPA);
                    const uint32_t vrow = (uint32_t)((ch*32 + kst*16)*KSTR);
                    #pragma unroll
                    for (int np = 0; np < 4; np++) {
                        uint32_t vb[4];
                        LDSM4T(vb[0], vb[1], vb[2], vb[3],
                               VB + vrow + (uint32_t)(np*32) + offVB);
                        mma16(o[2*np],   a, vb);
                        mma16(o[2*np+1], a, vb+2);
                    }
                }
                __syncwarp();
            }
            BARG(g+1);
            p ^= 1;
        }

        if (myfirst < myend) {
            l0 += __shfl_xor_sync(0xffffffffu, l0, 1);
            l0 += __shfl_xor_sync(0xffffffffu, l0, 2);
            l1 += __shfl_xor_sync(0xffffffffu, l1, 1);
            l1 += __shfl_xor_sync(0xffffffffu, l1, 2);
            float* Ob = g_Opart + ((size_t)(bb*32 + qt)*128) * 64;
            const int r0 = wrow + qr, r1 = r0 + 8;
            #pragma unroll
            for (int nt = 0; nt < 8; nt++) {
                int col = nt*8 + 2*m;
                atomicAdd(&Ob[r0*64 + col],     o[nt][0]);
                atomicAdd(&Ob[r0*64 + col + 1], o[nt][1]);
                atomicAdd(&Ob[r1*64 + col],     o[nt][2]);
                atomicAdd(&Ob[r1*64 + col + 1], o[nt][3]);
            }
            if (m == 0) {
                atomicAdd(&g_lpart[(bb*32 + qt)*128 + r0], l0);
                atomicAdd(&g_lpart[(bb*32 + qt)*128 + r1], l1);
            }
        }
        u += take;
    }
}

// ---------------------------------------------------------------------------
extern "C" void kernel_launch(void* const* d_in, const int* in_sizes, int n_in,
                              void* d_out, int out_size)
{
    const float* x  = (const float*)d_in[0];
    const float* Wq = (const float*)d_in[1];
    const float* Wk = (const float*)d_in[2];
    const float* Wv = (const float*)d_in[3];
    float* out = (float*)d_out;

    cudaFuncSetAttribute(qkv_tc,  cudaFuncAttributeMaxDynamicSharedMemorySize, QKV_SMEM);
    cudaFuncSetAttribute(attn_tc, cudaFuncAttributeMaxDynamicSharedMemorySize, ATT_SMEM);

    prep<<<520, 512>>>(Wq, Wk, Wv);
    qkv_tc<<<128, 512, QKV_SMEM>>>(x);
    attn_tc<<<NCTA, 512, ATT_SMEM>>>();
    attn_epi<<<512, 512>>>(out);
}